// round 1
// baseline (speedup 1.0000x reference)
#include <cuda_runtime.h>
#include <cstdint>

#define BATCH 4096
#define NCLS  200
#define NPPC  32
#define NFEAT 512
#define NPROT (NCLS*NPPC)     // 6400
#define ALPHA_F 5.0f
#define EPS_F   1e-8f

#define BM 128
#define BN 128
#define BK 16

// Scratch (static device globals -- no runtime allocation)
__device__ unsigned long long g_minpack[(size_t)BATCH * NCLS]; // packed (d2ord<<32)|proto
__device__ float g_p2[NPROT];
__device__ float g_rowsums[2 * BATCH];

// Order-preserving float->uint map (handles negatives too)
__device__ __forceinline__ unsigned int f2ord(float f) {
    unsigned int u = __float_as_uint(f);
    return (u & 0x80000000u) ? ~u : (u | 0x80000000u);
}

__global__ void init_kernel() {
    int n = BATCH * NCLS;
    int stride = gridDim.x * blockDim.x;
    for (int i = blockIdx.x * blockDim.x + threadIdx.x; i < n; i += stride)
        g_minpack[i] = ~0ull;
}

__global__ __launch_bounds__(128) void p2_kernel(const float* __restrict__ W) {
    int p = blockIdx.x;
    const float* row = W + (size_t)p * NFEAT;
    float s = 0.f;
    for (int i = threadIdx.x; i < NFEAT; i += 128) { float v = row[i]; s += v * v; }
    __shared__ float sh[4];
    int lane = threadIdx.x & 31, w = threadIdx.x >> 5;
    #pragma unroll
    for (int o = 16; o; o >>= 1) s += __shfl_down_sync(0xffffffffu, s, o);
    if (lane == 0) sh[w] = s;
    __syncthreads();
    if (threadIdx.x == 0) g_p2[p] = sh[0] + sh[1] + sh[2] + sh[3];
}

// Fused GEMM + per-class min/argmin epilogue.
// s[b,n] = p2[n] - 2*dot(x[b], w[n])  (x2[b] dropped: constant per row, argmin-invariant)
__global__ __launch_bounds__(256) void dist_kernel(const float* __restrict__ X,
                                                   const float* __restrict__ W) {
    __shared__ __align__(16) float sA[BK][BM + 4]; // transposed: sA[k][m]
    __shared__ __align__(16) float sB[BK][BN + 4]; // transposed: sB[k][n]

    int m0 = blockIdx.y * BM;
    int n0 = blockIdx.x * BN;
    int t  = threadIdx.x;
    int tx = t & 15;   // col group
    int ty = t >> 4;   // row group

    float acc[8][8];
    #pragma unroll
    for (int i = 0; i < 8; i++)
        #pragma unroll
        for (int j = 0; j < 8; j++) acc[i][j] = 0.f;

    for (int kt = 0; kt < NFEAT; kt += BK) {
        // Load 128x16 tiles of A and B, transposed into shared (coalesced float4 loads)
        #pragma unroll
        for (int it = 0; it < 2; it++) {
            int idx4 = t + it * 256;       // 0..511
            int r   = idx4 >> 2;           // 0..127
            int c4  = idx4 & 3;            // 0..3 (float4 within 16 k-cols)
            float4 va = *reinterpret_cast<const float4*>(X + (size_t)(m0 + r) * NFEAT + kt + c4 * 4);
            sA[c4 * 4 + 0][r] = va.x; sA[c4 * 4 + 1][r] = va.y;
            sA[c4 * 4 + 2][r] = va.z; sA[c4 * 4 + 3][r] = va.w;
            float4 vb = *reinterpret_cast<const float4*>(W + (size_t)(n0 + r) * NFEAT + kt + c4 * 4);
            sB[c4 * 4 + 0][r] = vb.x; sB[c4 * 4 + 1][r] = vb.y;
            sB[c4 * 4 + 2][r] = vb.z; sB[c4 * 4 + 3][r] = vb.w;
        }
        __syncthreads();

        #pragma unroll
        for (int k = 0; k < BK; k++) {
            float4 a0 = *reinterpret_cast<const float4*>(&sA[k][ty * 4]);
            float4 a1 = *reinterpret_cast<const float4*>(&sA[k][64 + ty * 4]);
            float4 b0 = *reinterpret_cast<const float4*>(&sB[k][tx * 4]);
            float4 b1 = *reinterpret_cast<const float4*>(&sB[k][64 + tx * 4]);
            float rA[8] = {a0.x, a0.y, a0.z, a0.w, a1.x, a1.y, a1.z, a1.w};
            float rB[8] = {b0.x, b0.y, b0.z, b0.w, b1.x, b1.y, b1.z, b1.w};
            #pragma unroll
            for (int i = 0; i < 8; i++)
                #pragma unroll
                for (int j = 0; j < 8; j++)
                    acc[i][j] = fmaf(rA[i], rB[j], acc[i][j]);
        }
        __syncthreads();
    }

    // Epilogue: per (row, class) packed min-reduce, then atomicMin into g_minpack.
    // Thread cols: j<4 -> n0 + tx*4 + j  (classes n0/32 + tx/8)
    //              j>=4 -> n0 + 64 + tx*4 + (j-4)
    // Each half's 4 cols live in ONE class; 8 tx-lanes (contiguous) share a class.
    #pragma unroll
    for (int i = 0; i < 8; i++) {
        int row = m0 + ((i < 4) ? (ty * 4 + i) : (64 + ty * 4 + (i - 4)));
        #pragma unroll
        for (int h = 0; h < 2; h++) {
            unsigned long long best = ~0ull;
            #pragma unroll
            for (int q = 0; q < 4; q++) {
                int j = h * 4 + q;
                int ncol = n0 + h * 64 + tx * 4 + q;
                float s = g_p2[ncol] - 2.0f * acc[i][j];
                unsigned long long pk =
                    ((unsigned long long)f2ord(s) << 32) | (unsigned long long)(unsigned)ncol;
                best = (pk < best) ? pk : best;
            }
            #pragma unroll
            for (int o = 4; o; o >>= 1) {
                unsigned long long v = __shfl_down_sync(0xffffffffu, best, o, 8);
                best = (v < best) ? v : best;
            }
            if ((tx & 7) == 0) {
                int cls = (n0 + h * 64 + (tx >> 3) * 32) >> 5;
                atomicMin(&g_minpack[(size_t)row * NCLS + cls], best);
            }
        }
    }
}

// Per row: target-class entry, masked cross-class min, exact distance recompute.
__global__ __launch_bounds__(256) void select_kernel(const float* __restrict__ X,
                                                     const float* __restrict__ W,
                                                     const int* __restrict__ tgt) {
    int row = blockIdx.x;
    int t = threadIdx.x;
    int target = tgt[row];

    __shared__ unsigned long long shm[256];
    __shared__ unsigned long long sh_t;

    unsigned long long best = ~0ull;
    for (int c = t; c < NCLS; c += 256) {
        unsigned long long v = g_minpack[(size_t)row * NCLS + c];
        if (c == target) sh_t = v;
        else best = (v < best) ? v : best;
    }
    shm[t] = best;
    __syncthreads();
    #pragma unroll
    for (int o = 128; o; o >>= 1) {
        if (t < o) { unsigned long long v = shm[t + o]; if (v < shm[t]) shm[t] = v; }
        __syncthreads();
    }

    int actual_n = (int)(unsigned)(sh_t & 0xffffffffull);
    int wrong_n  = (int)(unsigned)(shm[0] & 0xffffffffull);

    const float* xa = X + (size_t)row * NFEAT;
    const float* pa = W + (size_t)actual_n * NFEAT;
    const float* pw = W + (size_t)wrong_n  * NFEAT;
    float ts = 0.f, ws = 0.f;
    for (int f = t; f < NFEAT; f += 256) {
        float x = xa[f];
        float da = x - pa[f]; ts += da * da;
        float dw = x - pw[f]; ws += dw * dw;
    }
    __shared__ float shf[2][8];
    int lane = t & 31, w = t >> 5;
    #pragma unroll
    for (int o = 16; o; o >>= 1) {
        ts += __shfl_down_sync(0xffffffffu, ts, o);
        ws += __shfl_down_sync(0xffffffffu, ws, o);
    }
    if (lane == 0) { shf[0][w] = ts; shf[1][w] = ws; }
    __syncthreads();
    if (t == 0) {
        float a = 0.f, b = 0.f;
        #pragma unroll
        for (int i = 0; i < 8; i++) { a += shf[0][i]; b += shf[1][i]; }
        g_rowsums[row] = a;
        g_rowsums[BATCH + row] = b;
    }
}

__global__ __launch_bounds__(256) void final_kernel(float* __restrict__ out) {
    int t = threadIdx.x;
    float ta = 0.f, wa = 0.f;
    for (int r = t; r < BATCH; r += 256) { ta += g_rowsums[r]; wa += g_rowsums[BATCH + r]; }
    __shared__ float sh[2][8];
    int lane = t & 31, w = t >> 5;
    #pragma unroll
    for (int o = 16; o; o >>= 1) {
        ta += __shfl_down_sync(0xffffffffu, ta, o);
        wa += __shfl_down_sync(0xffffffffu, wa, o);
    }
    if (lane == 0) { sh[0][w] = ta; sh[1][w] = wa; }
    __syncthreads();
    if (t == 0) {
        float ts = 0.f, ws = 0.f;
        #pragma unroll
        for (int i = 0; i < 8; i++) { ts += sh[0][i]; ws += sh[1][i]; }
        float denom = (float)BATCH * (float)NFEAT;
        float tl  = ts / denom;
        float ntl = ws / denom;
        out[0] = (1.0f - ALPHA_F) * tl + ALPHA_F * (1.0f / (ntl + EPS_F));
    }
}

extern "C" void kernel_launch(void* const* d_in, const int* in_sizes, int n_in,
                              void* d_out, int out_size) {
    const float* X   = (const float*)d_in[0];   // outputs [4096, 512]
    const float* W   = (const float*)d_in[1];   // clusters [200*32, 512]
    const int*   tgt = (const int*)d_in[2];     // target_classes [4096]
    float* out = (float*)d_out;

    init_kernel<<<256, 256>>>();
    p2_kernel<<<NPROT, 128>>>(W);
    dim3 grid(NPROT / BN, BATCH / BM);
    dist_kernel<<<grid, 256>>>(X, W);
    select_kernel<<<BATCH, 256>>>(X, W, tgt);
    final_kernel<<<1, 256>>>(out);
}

// round 3
// speedup vs baseline: 3.8655x; 3.8655x over previous
#include <cuda_runtime.h>
#include <cuda_bf16.h>
#include <cstdint>

#define BATCH 4096
#define NCLS  200
#define NFEAT 512
#define NPROT 6400
#define ALPHA_F 5.0f
#define EPS_F   1e-8f

#define BM 128
#define BN 128
#define KC 64                 // bf16 per K-chunk = 128 bytes/row
#define NCHUNK (NFEAT / KC)   // 8

// ---------------- device scratch (no runtime allocation) ----------------
__device__ __align__(16) __nv_bfloat16 g_Xb[(size_t)BATCH * NFEAT];
__device__ __align__(16) __nv_bfloat16 g_Wb[(size_t)NPROT * NFEAT];
__device__ float g_p2[NPROT];
__device__ unsigned long long g_minpack[(size_t)BATCH * NCLS];
__device__ float g_rowsums[2 * BATCH];

// ---------------- helpers ----------------
__device__ __forceinline__ uint32_t smem_u32(const void* p) {
    uint32_t a;
    asm("{ .reg .u64 t; cvta.to.shared.u64 t, %1; cvt.u32.u64 %0, t; }" : "=r"(a) : "l"(p));
    return a;
}
__device__ __forceinline__ void cp16(uint32_t s, const void* g) {
    asm volatile("cp.async.cg.shared.global [%0], [%1], 16;" :: "r"(s), "l"(g));
}
__device__ __forceinline__ void ldsm4(uint32_t* r, uint32_t addr) {
    asm volatile("ldmatrix.sync.aligned.m8n8.x4.shared.b16 {%0,%1,%2,%3}, [%4];"
                 : "=r"(r[0]), "=r"(r[1]), "=r"(r[2]), "=r"(r[3]) : "r"(addr));
}
__device__ __forceinline__ void mma16816(float* c, const uint32_t* a, const uint32_t* b) {
    asm volatile("mma.sync.aligned.m16n8k16.row.col.f32.bf16.bf16.f32 "
                 "{%0,%1,%2,%3}, {%4,%5,%6,%7}, {%8,%9}, {%0,%1,%2,%3};"
                 : "+f"(c[0]), "+f"(c[1]), "+f"(c[2]), "+f"(c[3])
                 : "r"(a[0]), "r"(a[1]), "r"(a[2]), "r"(a[3]), "r"(b[0]), "r"(b[1]));
}
// order-preserving float -> uint
__device__ __forceinline__ unsigned int f2ord(float f) {
    unsigned int u = __float_as_uint(f);
    return (u & 0x80000000u) ? ~u : (u | 0x80000000u);
}

// ---------------- convert kernels ----------------
__global__ __launch_bounds__(256) void conv_x_kernel(const float* __restrict__ X) {
    int idx = blockIdx.x * blockDim.x + threadIdx.x;
    int total = BATCH * NFEAT / 4;
    int stride = gridDim.x * blockDim.x;
    for (; idx < total; idx += stride) {
        float4 v = reinterpret_cast<const float4*>(X)[idx];
        __nv_bfloat162 lo = __nv_bfloat162(__float2bfloat16_rn(v.x), __float2bfloat16_rn(v.y));
        __nv_bfloat162 hi = __nv_bfloat162(__float2bfloat16_rn(v.z), __float2bfloat16_rn(v.w));
        uint2 pk;
        pk.x = *reinterpret_cast<uint32_t*>(&lo);
        pk.y = *reinterpret_cast<uint32_t*>(&hi);
        reinterpret_cast<uint2*>(g_Xb)[idx] = pk;
    }
}

__global__ __launch_bounds__(128) void conv_w_kernel(const float* __restrict__ W) {
    int p = blockIdx.x;
    int t = threadIdx.x;
    const float4 v = reinterpret_cast<const float4*>(W + (size_t)p * NFEAT)[t];
    __nv_bfloat162 lo = __nv_bfloat162(__float2bfloat16_rn(v.x), __float2bfloat16_rn(v.y));
    __nv_bfloat162 hi = __nv_bfloat162(__float2bfloat16_rn(v.z), __float2bfloat16_rn(v.w));
    uint2 pk;
    pk.x = *reinterpret_cast<uint32_t*>(&lo);
    pk.y = *reinterpret_cast<uint32_t*>(&hi);
    reinterpret_cast<uint2*>(g_Wb + (size_t)p * NFEAT)[t] = pk;

    float s = v.x * v.x + v.y * v.y + v.z * v.z + v.w * v.w;
    __shared__ float sh[4];
    int lane = t & 31, w = t >> 5;
    #pragma unroll
    for (int o = 16; o; o >>= 1) s += __shfl_down_sync(0xffffffffu, s, o);
    if (lane == 0) sh[w] = s;
    __syncthreads();
    if (t == 0) g_p2[p] = sh[0] + sh[1] + sh[2] + sh[3];
}

// ---------------- fused bf16 HMMA GEMM + per-class argmin ----------------
// dynamic smem: [0,512): p2 tile; [1024 .. 1024+64K): A0,A1,B0,B1 (16KB each)
#define SM_P2   0
#define SM_A    1024
#define SM_B    (1024 + 32768)
#define TILE_B  16384
#define SMEM_TOTAL (1024 + 65536)

__global__ __launch_bounds__(256, 1) void dist_kernel() {
    extern __shared__ char smem[];
    uint32_t sb = smem_u32(smem);
    const int tid = threadIdx.x;
    const int lane = tid & 31;
    const int wid = tid >> 5;
    const int wm = wid & 1;      // M half (0/1): rows wm*64..+63
    const int wn = wid >> 1;     // N quarter (0..3): cols wn*32..+31 == one class
    const int n0 = blockIdx.x * BN;
    const int m0 = blockIdx.y * BM;

    // p2 tile -> smem
    if (tid < 128) reinterpret_cast<float*>(smem + SM_P2)[tid] = g_p2[n0 + tid];

    // ---- cp.async loader mapping: thread -> (row = tid>>1, half = tid&1) ----
    const int lrow = tid >> 1;           // 0..127
    const int lhalf = tid & 1;           // chunk base = lhalf*4
    const __nv_bfloat16* gA = g_Xb + (size_t)(m0 + lrow) * NFEAT + lhalf * 32;
    const __nv_bfloat16* gB = g_Wb + (size_t)(n0 + lrow) * NFEAT + lhalf * 32;
    uint32_t sArow = sb + SM_A + lrow * 128;
    uint32_t sBrow = sb + SM_B + lrow * 128;
    const int rsw = lrow & 7;

    // prologue: load chunk 0 into buf 0
    #pragma unroll
    for (int q = 0; q < 4; q++) {
        int chunk = lhalf * 4 + q;
        uint32_t soff = (uint32_t)((chunk ^ rsw) << 4);
        cp16(sArow + soff, gA + q * 8);
        cp16(sBrow + soff, gB + q * 8);
    }
    asm volatile("cp.async.commit_group;" ::: "memory");

    // ---- ldmatrix lane addressing ----
    const int lr = lane & 7;
    const int lm = lane >> 3;
    // A: tile i rows wm*64 + i*16 + (lm&1)*8 + lr ; chunk = ks*2 + (lm>>1)
    const int a_rbase = wm * 64 + (lm & 1) * 8 + lr;
    const int a_chi = lm >> 1;
    // B: tile-pair j2 rows wn*32 + j2*16 + (lm>>1)*8 + lr ; chunk = ks*2 + (lm&1)
    const int b_rbase = wn * 32 + (lm >> 1) * 8 + lr;
    const int b_chi = lm & 1;

    float acc[4][4][4];
    #pragma unroll
    for (int i = 0; i < 4; i++)
        #pragma unroll
        for (int j = 0; j < 4; j++)
            #pragma unroll
            for (int k = 0; k < 4; k++) acc[i][j][k] = 0.f;

    for (int c = 0; c < NCHUNK; c++) {
        // issue next chunk's loads into the other buffer
        if (c + 1 < NCHUNK) {
            int nb = (c + 1) & 1;
            const __nv_bfloat16* gA2 = gA + (c + 1) * KC;
            const __nv_bfloat16* gB2 = gB + (c + 1) * KC;
            #pragma unroll
            for (int q = 0; q < 4; q++) {
                int chunk = lhalf * 4 + q;
                uint32_t soff = (uint32_t)(nb * TILE_B + ((chunk ^ rsw) << 4));
                cp16(sArow + soff, gA2 + q * 8);
                cp16(sBrow + soff, gB2 + q * 8);
            }
            asm volatile("cp.async.commit_group;" ::: "memory");
            asm volatile("cp.async.wait_group 1;" ::: "memory");
        } else {
            asm volatile("cp.async.wait_group 0;" ::: "memory");
        }
        __syncthreads();

        uint32_t bufA = sb + SM_A + (c & 1) * TILE_B;
        uint32_t bufB = sb + SM_B + (c & 1) * TILE_B;

        #pragma unroll
        for (int ks = 0; ks < 4; ks++) {
            uint32_t afr[4][4], bfr[2][4];
            #pragma unroll
            for (int i = 0; i < 4; i++) {
                int r = a_rbase + i * 16;
                int ch = ks * 2 + a_chi;
                ldsm4(afr[i], bufA + r * 128 + ((ch ^ (r & 7)) << 4));
            }
            #pragma unroll
            for (int j2 = 0; j2 < 2; j2++) {
                int r = b_rbase + j2 * 16;
                int ch = ks * 2 + b_chi;
                ldsm4(bfr[j2], bufB + r * 128 + ((ch ^ (r & 7)) << 4));
            }
            #pragma unroll
            for (int i = 0; i < 4; i++)
                #pragma unroll
                for (int j = 0; j < 4; j++)
                    mma16816(acc[i][j], afr[i], bfr[j >> 1] + (j & 1) * 2);
        }
        __syncthreads();
    }

    // ---- epilogue: per-(row,class) packed argmin, plain store ----
    const float* sp2 = reinterpret_cast<const float*>(smem + SM_P2);
    const int cls = (n0 >> 5) + wn;              // global class index
    const int colb = wn * 32 + 2 * (lane & 3);   // within-tile col base for this thread

    #pragma unroll
    for (int i = 0; i < 4; i++) {
        unsigned long long plo = ~0ull, phi = ~0ull;
        #pragma unroll
        for (int j = 0; j < 4; j++) {
            #pragma unroll
            for (int t = 0; t < 2; t++) {
                int colt = colb + j * 8 + t;
                float p2v = sp2[colt];
                unsigned nidx = (unsigned)(n0 + colt);
                float slo = p2v - 2.0f * acc[i][j][t];
                unsigned long long pk1 = ((unsigned long long)f2ord(slo) << 32) | nidx;
                plo = (pk1 < plo) ? pk1 : plo;
                float shi = p2v - 2.0f * acc[i][j][2 + t];
                unsigned long long pk2 = ((unsigned long long)f2ord(shi) << 32) | nidx;
                phi = (pk2 < phi) ? pk2 : phi;
            }
        }
        // reduce across the quad (lane&3 spans cols)
        #pragma unroll
        for (int o = 1; o <= 2; o <<= 1) {
            unsigned long long v1 = __shfl_xor_sync(0xffffffffu, plo, o);
            plo = (v1 < plo) ? v1 : plo;
            unsigned long long v2 = __shfl_xor_sync(0xffffffffu, phi, o);
            phi = (v2 < phi) ? v2 : phi;
        }
        if ((lane & 3) == 0) {
            int row = m0 + wm * 64 + i * 16 + (lane >> 2);
            g_minpack[(size_t)row * NCLS + cls] = plo;
            g_minpack[(size_t)(row + 8) * NCLS + cls] = phi;
        }
    }
}

// ---------------- per-row selection + exact distance recompute ----------------
__global__ __launch_bounds__(256) void select_kernel(const float* __restrict__ X,
                                                     const float* __restrict__ W,
                                                     const int* __restrict__ tgt) {
    int row = blockIdx.x;
    int t = threadIdx.x;
    int target = tgt[row];

    __shared__ unsigned long long shm[256];
    __shared__ unsigned long long sh_t;

    unsigned long long best = ~0ull;
    for (int c = t; c < NCLS; c += 256) {
        unsigned long long v = g_minpack[(size_t)row * NCLS + c];
        if (c == target) sh_t = v;
        else best = (v < best) ? v : best;
    }
    shm[t] = best;
    __syncthreads();
    #pragma unroll
    for (int o = 128; o; o >>= 1) {
        if (t < o) { unsigned long long v = shm[t + o]; if (v < shm[t]) shm[t] = v; }
        __syncthreads();
    }

    int actual_n = (int)(unsigned)(sh_t & 0xffffffffull);
    int wrong_n  = (int)(unsigned)(shm[0] & 0xffffffffull);

    const float* xa = X + (size_t)row * NFEAT;
    const float* pa = W + (size_t)actual_n * NFEAT;
    const float* pw = W + (size_t)wrong_n  * NFEAT;
    float ts = 0.f, ws = 0.f;
    for (int f = t; f < NFEAT; f += 256) {
        float x = xa[f];
        float da = x - pa[f]; ts += da * da;
        float dw = x - pw[f]; ws += dw * dw;
    }
    __shared__ float shf[2][8];
    int lane = t & 31, w = t >> 5;
    #pragma unroll
    for (int o = 16; o; o >>= 1) {
        ts += __shfl_down_sync(0xffffffffu, ts, o);
        ws += __shfl_down_sync(0xffffffffu, ws, o);
    }
    if (lane == 0) { shf[0][w] = ts; shf[1][w] = ws; }
    __syncthreads();
    if (t == 0) {
        float a = 0.f, b = 0.f;
        #pragma unroll
        for (int i = 0; i < 8; i++) { a += shf[0][i]; b += shf[1][i]; }
        g_rowsums[row] = a;
        g_rowsums[BATCH + row] = b;
    }
}

__global__ __launch_bounds__(256) void final_kernel(float* __restrict__ out) {
    int t = threadIdx.x;
    float ta = 0.f, wa = 0.f;
    for (int r = t; r < BATCH; r += 256) { ta += g_rowsums[r]; wa += g_rowsums[BATCH + r]; }
    __shared__ float sh[2][8];
    int lane = t & 31, w = t >> 5;
    #pragma unroll
    for (int o = 16; o; o >>= 1) {
        ta += __shfl_down_sync(0xffffffffu, ta, o);
        wa += __shfl_down_sync(0xffffffffu, wa, o);
    }
    if (lane == 0) { sh[0][w] = ta; sh[1][w] = wa; }
    __syncthreads();
    if (t == 0) {
        float ts = 0.f, ws = 0.f;
        #pragma unroll
        for (int i = 0; i < 8; i++) { ts += sh[0][i]; ws += sh[1][i]; }
        float denom = (float)BATCH * (float)NFEAT;
        float tl  = ts / denom;
        float ntl = ws / denom;
        out[0] = (1.0f - ALPHA_F) * tl + ALPHA_F * (1.0f / (ntl + EPS_F));
    }
}

extern "C" void kernel_launch(void* const* d_in, const int* in_sizes, int n_in,
                              void* d_out, int out_size) {
    const float* X   = (const float*)d_in[0];   // outputs [4096, 512]
    const float* W   = (const float*)d_in[1];   // clusters [6400, 512]
    const int*   tgt = (const int*)d_in[2];     // target_classes [4096]
    float* out = (float*)d_out;

    cudaFuncSetAttribute(dist_kernel, cudaFuncAttributeMaxDynamicSharedMemorySize, SMEM_TOTAL);

    conv_x_kernel<<<512, 256>>>(X);
    conv_w_kernel<<<NPROT, 128>>>(W);
    dim3 grid(NPROT / BN, BATCH / BM);   // (50, 32)
    dist_kernel<<<grid, 256, SMEM_TOTAL>>>();
    select_kernel<<<BATCH, 256>>>(X, W, tgt);
    final_kernel<<<1, 256>>>(out);
}

// round 4
// speedup vs baseline: 5.4152x; 1.4009x over previous
#include <cuda_runtime.h>
#include <cuda_bf16.h>
#include <cstdint>

#define BATCH 4096
#define NCLS  200
#define NFEAT 512
#define NPROT 6400
#define ALPHA_F 5.0f
#define EPS_F   1e-8f

#define BM 128
#define BN 256
#define KC 64                 // bf16 per K-chunk = 128 bytes/row
#define NCHUNK (NFEAT / KC)   // 8

// ---------------- device scratch (no runtime allocation) ----------------
__device__ __align__(16) __nv_bfloat16 g_Xb[(size_t)BATCH * NFEAT];
__device__ __align__(16) __nv_bfloat16 g_Wb[(size_t)NPROT * NFEAT];
__device__ float g_p2[NPROT];
__device__ unsigned long long g_minpack[(size_t)BATCH * NCLS];
__device__ float g_rowsums[2 * BATCH];

// ---------------- helpers ----------------
__device__ __forceinline__ uint32_t smem_u32(const void* p) {
    uint32_t a;
    asm("{ .reg .u64 t; cvta.to.shared.u64 t, %1; cvt.u32.u64 %0, t; }" : "=r"(a) : "l"(p));
    return a;
}
__device__ __forceinline__ void cp16(uint32_t s, const void* g) {
    asm volatile("cp.async.cg.shared.global [%0], [%1], 16;" :: "r"(s), "l"(g));
}
__device__ __forceinline__ void ldsm4(uint32_t* r, uint32_t addr) {
    asm volatile("ldmatrix.sync.aligned.m8n8.x4.shared.b16 {%0,%1,%2,%3}, [%4];"
                 : "=r"(r[0]), "=r"(r[1]), "=r"(r[2]), "=r"(r[3]) : "r"(addr));
}
__device__ __forceinline__ void mma16816(float* c, const uint32_t* a, const uint32_t* b) {
    asm volatile("mma.sync.aligned.m16n8k16.row.col.f32.bf16.bf16.f32 "
                 "{%0,%1,%2,%3}, {%4,%5,%6,%7}, {%8,%9}, {%0,%1,%2,%3};"
                 : "+f"(c[0]), "+f"(c[1]), "+f"(c[2]), "+f"(c[3])
                 : "r"(a[0]), "r"(a[1]), "r"(a[2]), "r"(a[3]), "r"(b[0]), "r"(b[1]));
}
__device__ __forceinline__ unsigned int f2ord(float f) {
    unsigned int u = __float_as_uint(f);
    return (u & 0x80000000u) ? ~u : (u | 0x80000000u);
}
__device__ __forceinline__ unsigned long long umin64(unsigned long long a, unsigned long long b) {
    return a < b ? a : b;
}

// ---------------- convert kernels ----------------
__global__ __launch_bounds__(256) void conv_x_kernel(const float* __restrict__ X) {
    int idx = blockIdx.x * blockDim.x + threadIdx.x;
    int total = BATCH * NFEAT / 4;
    int stride = gridDim.x * blockDim.x;
    for (; idx < total; idx += stride) {
        float4 v = reinterpret_cast<const float4*>(X)[idx];
        __nv_bfloat162 lo = __nv_bfloat162(__float2bfloat16_rn(v.x), __float2bfloat16_rn(v.y));
        __nv_bfloat162 hi = __nv_bfloat162(__float2bfloat16_rn(v.z), __float2bfloat16_rn(v.w));
        uint2 pk;
        pk.x = *reinterpret_cast<uint32_t*>(&lo);
        pk.y = *reinterpret_cast<uint32_t*>(&hi);
        reinterpret_cast<uint2*>(g_Xb)[idx] = pk;
    }
}

__global__ __launch_bounds__(128) void conv_w_kernel(const float* __restrict__ W) {
    int p = blockIdx.x;
    int t = threadIdx.x;
    const float4 v = reinterpret_cast<const float4*>(W + (size_t)p * NFEAT)[t];
    __nv_bfloat162 lo = __nv_bfloat162(__float2bfloat16_rn(v.x), __float2bfloat16_rn(v.y));
    __nv_bfloat162 hi = __nv_bfloat162(__float2bfloat16_rn(v.z), __float2bfloat16_rn(v.w));
    uint2 pk;
    pk.x = *reinterpret_cast<uint32_t*>(&lo);
    pk.y = *reinterpret_cast<uint32_t*>(&hi);
    reinterpret_cast<uint2*>(g_Wb + (size_t)p * NFEAT)[t] = pk;

    float s = v.x * v.x + v.y * v.y + v.z * v.z + v.w * v.w;
    __shared__ float sh[4];
    int lane = t & 31, w = t >> 5;
    #pragma unroll
    for (int o = 16; o; o >>= 1) s += __shfl_down_sync(0xffffffffu, s, o);
    if (lane == 0) sh[w] = s;
    __syncthreads();
    if (t == 0) g_p2[p] = sh[0] + sh[1] + sh[2] + sh[3];
}

// ---------------- fused bf16 HMMA GEMM + per-class argmin ----------------
// dynamic smem: [0,1024): p2 tile (256 f32); A: 2 x 16KB; B: 2 x 32KB
#define SM_P2    0
#define SM_A     1024
#define SM_B     (1024 + 32768)
#define TILE_A   16384
#define TILE_BB  32768
#define SMEM_TOTAL (1024 + 32768 + 65536)   // 99328

__global__ __launch_bounds__(256, 1) void dist_kernel() {
    extern __shared__ char smem[];
    uint32_t sb = smem_u32(smem);
    const int tid = threadIdx.x;
    const int lane = tid & 31;
    const int wid = tid >> 5;
    const int wm = wid & 1;      // M half (0/1): rows wm*64..+63
    const int wn = wid >> 1;     // N quarter (0..3): cols wn*64..+63 == 2 classes
    const int n0 = blockIdx.x * BN;
    const int m0 = blockIdx.y * BM;

    // p2 tile -> smem
    reinterpret_cast<float*>(smem + SM_P2)[tid] = g_p2[n0 + tid];

    // ---- cp.async loader: i = tid&7 (16B slot), r0 = tid>>3 (row mod 32) ----
    const int li = tid & 7;
    const int r0 = tid >> 3;             // 0..31
    const uint32_t swo = (uint32_t)((li ^ (r0 & 7)) << 4);   // constant per thread
    const __nv_bfloat16* gA = g_Xb + (size_t)(m0 + r0) * NFEAT + li * 8;
    const __nv_bfloat16* gB = g_Wb + (size_t)(n0 + r0) * NFEAT + li * 8;
    uint32_t sA0 = sb + SM_A + r0 * 128 + swo;
    uint32_t sB0 = sb + SM_B + r0 * 128 + swo;

    // prologue: chunk 0 -> buffer 0
    #pragma unroll
    for (int it = 0; it < 4; it++)
        cp16(sA0 + it * (32 * 128), gA + (size_t)it * 32 * NFEAT);
    #pragma unroll
    for (int it = 0; it < 8; it++)
        cp16(sB0 + it * (32 * 128), gB + (size_t)it * 32 * NFEAT);
    asm volatile("cp.async.commit_group;" ::: "memory");

    // ---- ldmatrix lane addressing ----
    const int lr = lane & 7;
    const int lm = lane >> 3;
    const int a_rbase = wm * 64 + (lm & 1) * 8 + lr;
    const int a_chi = lm >> 1;
    const int b_rbase = wn * 64 + (lm >> 1) * 8 + lr;
    const int b_chi = lm & 1;

    float acc[4][8][4];
    #pragma unroll
    for (int i = 0; i < 4; i++)
        #pragma unroll
        for (int j = 0; j < 8; j++)
            #pragma unroll
            for (int k = 0; k < 4; k++) acc[i][j][k] = 0.f;

    for (int c = 0; c < NCHUNK; c++) {
        if (c + 1 < NCHUNK) {
            int nb = (c + 1) & 1;
            const __nv_bfloat16* gA2 = gA + (c + 1) * KC;
            const __nv_bfloat16* gB2 = gB + (c + 1) * KC;
            #pragma unroll
            for (int it = 0; it < 4; it++)
                cp16(sA0 + nb * TILE_A + it * (32 * 128), gA2 + (size_t)it * 32 * NFEAT);
            #pragma unroll
            for (int it = 0; it < 8; it++)
                cp16(sB0 + nb * TILE_BB + it * (32 * 128), gB2 + (size_t)it * 32 * NFEAT);
            asm volatile("cp.async.commit_group;" ::: "memory");
            asm volatile("cp.async.wait_group 1;" ::: "memory");
        } else {
            asm volatile("cp.async.wait_group 0;" ::: "memory");
        }
        __syncthreads();

        uint32_t bufA = sb + SM_A + (c & 1) * TILE_A;
        uint32_t bufB = sb + SM_B + (c & 1) * TILE_BB;

        #pragma unroll
        for (int ks = 0; ks < 4; ks++) {
            uint32_t afr[4][4], bfr[4][4];
            #pragma unroll
            for (int i = 0; i < 4; i++) {
                int r = a_rbase + i * 16;
                int ch = ks * 2 + a_chi;
                ldsm4(afr[i], bufA + r * 128 + ((ch ^ (r & 7)) << 4));
            }
            #pragma unroll
            for (int j2 = 0; j2 < 4; j2++) {
                int r = b_rbase + j2 * 16;
                int ch = ks * 2 + b_chi;
                ldsm4(bfr[j2], bufB + r * 128 + ((ch ^ (r & 7)) << 4));
            }
            #pragma unroll
            for (int i = 0; i < 4; i++)
                #pragma unroll
                for (int j = 0; j < 8; j++)
                    mma16816(acc[i][j], afr[i], bfr[j >> 1] + (j & 1) * 2);
        }
        __syncthreads();
    }

    // ---- epilogue: per-(row,class) packed argmin, plain store ----
    const float* sp2 = reinterpret_cast<const float*>(smem + SM_P2);
    const int cls0 = (n0 >> 5) + wn * 2;
    const int colq = 2 * (lane & 3);

    #pragma unroll
    for (int i = 0; i < 4; i++) {
        #pragma unroll
        for (int h = 0; h < 2; h++) {          // class within warp tile
            unsigned long long plo = ~0ull, phi = ~0ull;
            #pragma unroll
            for (int q = 0; q < 4; q++) {
                int j = h * 4 + q;
                #pragma unroll
                for (int t = 0; t < 2; t++) {
                    int colt = wn * 64 + j * 8 + colq + t;
                    float p2v = sp2[colt];
                    unsigned nidx = (unsigned)(n0 + colt);
                    float slo = p2v - 2.0f * acc[i][j][t];
                    plo = umin64(plo, ((unsigned long long)f2ord(slo) << 32) | nidx);
                    float shi = p2v - 2.0f * acc[i][j][2 + t];
                    phi = umin64(phi, ((unsigned long long)f2ord(shi) << 32) | nidx);
                }
            }
            #pragma unroll
            for (int o = 1; o <= 2; o <<= 1) {
                plo = umin64(plo, __shfl_xor_sync(0xffffffffu, plo, o));
                phi = umin64(phi, __shfl_xor_sync(0xffffffffu, phi, o));
            }
            if ((lane & 3) == 0) {
                int row = m0 + wm * 64 + i * 16 + (lane >> 2);
                g_minpack[(size_t)row * NCLS + cls0 + h] = plo;
                g_minpack[(size_t)(row + 8) * NCLS + cls0 + h] = phi;
            }
        }
    }
}

// ---------------- per-row selection: one warp per row ----------------
__global__ __launch_bounds__(256) void select_kernel(const float* __restrict__ X,
                                                     const float* __restrict__ W,
                                                     const int* __restrict__ tgt) {
    const int lane = threadIdx.x & 31;
    const int w = threadIdx.x >> 5;
    const int row = blockIdx.x * 8 + w;
    const int target = tgt[row];

    unsigned long long best = ~0ull, tpk = ~0ull;
    const unsigned long long* mp = g_minpack + (size_t)row * NCLS;
    #pragma unroll
    for (int c = lane; c < NCLS; c += 32) {
        unsigned long long v = mp[c];
        if (c == target) tpk = v;
        else best = umin64(best, v);
    }
    #pragma unroll
    for (int o = 16; o; o >>= 1) {
        best = umin64(best, __shfl_xor_sync(0xffffffffu, best, o));
        tpk  = umin64(tpk,  __shfl_xor_sync(0xffffffffu, tpk,  o));
    }

    int actual_n = (int)(unsigned)(tpk & 0xffffffffull);
    int wrong_n  = (int)(unsigned)(best & 0xffffffffull);

    const float4* xa = reinterpret_cast<const float4*>(X + (size_t)row * NFEAT);
    const float4* pa = reinterpret_cast<const float4*>(W + (size_t)actual_n * NFEAT);
    const float4* pw = reinterpret_cast<const float4*>(W + (size_t)wrong_n  * NFEAT);
    float ts = 0.f, ws = 0.f;
    #pragma unroll
    for (int f = lane; f < NFEAT / 4; f += 32) {
        float4 x = xa[f], a = pa[f], b = pw[f];
        float d;
        d = x.x - a.x; ts += d * d;  d = x.y - a.y; ts += d * d;
        d = x.z - a.z; ts += d * d;  d = x.w - a.w; ts += d * d;
        d = x.x - b.x; ws += d * d;  d = x.y - b.y; ws += d * d;
        d = x.z - b.z; ws += d * d;  d = x.w - b.w; ws += d * d;
    }
    #pragma unroll
    for (int o = 16; o; o >>= 1) {
        ts += __shfl_xor_sync(0xffffffffu, ts, o);
        ws += __shfl_xor_sync(0xffffffffu, ws, o);
    }
    if (lane == 0) {
        g_rowsums[row] = ts;
        g_rowsums[BATCH + row] = ws;
    }
}

__global__ __launch_bounds__(256) void final_kernel(float* __restrict__ out) {
    int t = threadIdx.x;
    float ta = 0.f, wa = 0.f;
    for (int r = t; r < BATCH; r += 256) { ta += g_rowsums[r]; wa += g_rowsums[BATCH + r]; }
    __shared__ float sh[2][8];
    int lane = t & 31, w = t >> 5;
    #pragma unroll
    for (int o = 16; o; o >>= 1) {
        ta += __shfl_down_sync(0xffffffffu, ta, o);
        wa += __shfl_down_sync(0xffffffffu, wa, o);
    }
    if (lane == 0) { sh[0][w] = ta; sh[1][w] = wa; }
    __syncthreads();
    if (t == 0) {
        float ts = 0.f, ws = 0.f;
        #pragma unroll
        for (int i = 0; i < 8; i++) { ts += sh[0][i]; ws += sh[1][i]; }
        float denom = (float)BATCH * (float)NFEAT;
        float tl  = ts / denom;
        float ntl = ws / denom;
        out[0] = (1.0f - ALPHA_F) * tl + ALPHA_F * (1.0f / (ntl + EPS_F));
    }
}

extern "C" void kernel_launch(void* const* d_in, const int* in_sizes, int n_in,
                              void* d_out, int out_size) {
    const float* X   = (const float*)d_in[0];   // outputs [4096, 512]
    const float* W   = (const float*)d_in[1];   // clusters [6400, 512]
    const int*   tgt = (const int*)d_in[2];     // target_classes [4096]
    float* out = (float*)d_out;

    cudaFuncSetAttribute(dist_kernel, cudaFuncAttributeMaxDynamicSharedMemorySize, SMEM_TOTAL);

    conv_x_kernel<<<512, 256>>>(X);
    conv_w_kernel<<<NPROT, 128>>>(W);
    dim3 grid(NPROT / BN, BATCH / BM);   // (25, 32)
    dist_kernel<<<grid, 256, SMEM_TOTAL>>>();
    select_kernel<<<BATCH / 8, 256>>>(X, W, tgt);
    final_kernel<<<1, 256>>>(out);
}

// round 5
// speedup vs baseline: 5.4304x; 1.0028x over previous
#include <cuda_runtime.h>
#include <cuda_bf16.h>
#include <cstdint>

#define BATCH 4096
#define NCLS  200
#define NFEAT 512
#define NPROT 6400
#define ALPHA_F 5.0f
#define EPS_F   1e-8f

#define BM 128
#define BN 256
#define KC 64                 // bf16 per K-chunk = 128 bytes/row
#define NCHUNK (NFEAT / KC)   // 8

// ---------------- device scratch (no runtime allocation) ----------------
__device__ __align__(16) __nv_bfloat16 g_Xb[(size_t)BATCH * NFEAT];
__device__ __align__(16) __nv_bfloat16 g_Wb[(size_t)NPROT * NFEAT];
__device__ float g_p2[NPROT];
__device__ unsigned long long g_minpack[(size_t)BATCH * NCLS];
__device__ float g_rowsums[2 * BATCH];

// ---------------- helpers ----------------
__device__ __forceinline__ uint32_t smem_u32(const void* p) {
    uint32_t a;
    asm("{ .reg .u64 t; cvta.to.shared.u64 t, %1; cvt.u32.u64 %0, t; }" : "=r"(a) : "l"(p));
    return a;
}
__device__ __forceinline__ void cp16(uint32_t s, const void* g) {
    asm volatile("cp.async.cg.shared.global [%0], [%1], 16;" :: "r"(s), "l"(g));
}
__device__ __forceinline__ void ldsm4(uint32_t* r, uint32_t addr) {
    asm volatile("ldmatrix.sync.aligned.m8n8.x4.shared.b16 {%0,%1,%2,%3}, [%4];"
                 : "=r"(r[0]), "=r"(r[1]), "=r"(r[2]), "=r"(r[3]) : "r"(addr));
}
__device__ __forceinline__ void mma16816(float* c, const uint32_t* a, const uint32_t* b) {
    asm volatile("mma.sync.aligned.m16n8k16.row.col.f32.bf16.bf16.f32 "
                 "{%0,%1,%2,%3}, {%4,%5,%6,%7}, {%8,%9}, {%0,%1,%2,%3};"
                 : "+f"(c[0]), "+f"(c[1]), "+f"(c[2]), "+f"(c[3])
                 : "r"(a[0]), "r"(a[1]), "r"(a[2]), "r"(a[3]), "r"(b[0]), "r"(b[1]));
}
__device__ __forceinline__ unsigned int f2ord(float f) {
    unsigned int u = __float_as_uint(f);
    return (u & 0x80000000u) ? ~u : (u | 0x80000000u);
}
__device__ __forceinline__ unsigned long long umin64(unsigned long long a, unsigned long long b) {
    return a < b ? a : b;
}

// ---------------- merged convert kernel ----------------
// blocks 0..3199: two W rows each (bf16 convert + p2)
// blocks 3200..3327: grid-stride bf16 convert of X
#define CONV_WBLKS 3200
#define CONV_XBLKS 128

__global__ __launch_bounds__(256) void conv_kernel(const float* __restrict__ X,
                                                   const float* __restrict__ W) {
    int b = blockIdx.x;
    if (b < CONV_WBLKS) {
        int half = threadIdx.x >> 7;          // 0/1: which W row
        int t = threadIdx.x & 127;
        int p = b * 2 + half;
        const float4 v = reinterpret_cast<const float4*>(W + (size_t)p * NFEAT)[t];
        __nv_bfloat162 lo = __nv_bfloat162(__float2bfloat16_rn(v.x), __float2bfloat16_rn(v.y));
        __nv_bfloat162 hi = __nv_bfloat162(__float2bfloat16_rn(v.z), __float2bfloat16_rn(v.w));
        uint2 pk;
        pk.x = *reinterpret_cast<uint32_t*>(&lo);
        pk.y = *reinterpret_cast<uint32_t*>(&hi);
        reinterpret_cast<uint2*>(g_Wb + (size_t)p * NFEAT)[t] = pk;

        float s = v.x * v.x + v.y * v.y + v.z * v.z + v.w * v.w;
        __shared__ float sh[8];
        int lane = threadIdx.x & 31, w = threadIdx.x >> 5;
        #pragma unroll
        for (int o = 16; o; o >>= 1) s += __shfl_down_sync(0xffffffffu, s, o);
        if (lane == 0) sh[w] = s;
        __syncthreads();
        if (t == 0)
            g_p2[p] = sh[half * 4] + sh[half * 4 + 1] + sh[half * 4 + 2] + sh[half * 4 + 3];
    } else {
        int idx = (b - CONV_WBLKS) * 256 + threadIdx.x;
        const int total = BATCH * NFEAT / 4;
        const int stride = CONV_XBLKS * 256;
        for (; idx < total; idx += stride) {
            float4 v = reinterpret_cast<const float4*>(X)[idx];
            __nv_bfloat162 lo = __nv_bfloat162(__float2bfloat16_rn(v.x), __float2bfloat16_rn(v.y));
            __nv_bfloat162 hi = __nv_bfloat162(__float2bfloat16_rn(v.z), __float2bfloat16_rn(v.w));
            uint2 pk;
            pk.x = *reinterpret_cast<uint32_t*>(&lo);
            pk.y = *reinterpret_cast<uint32_t*>(&hi);
            reinterpret_cast<uint2*>(g_Xb)[idx] = pk;
        }
    }
}

// ---------------- fused bf16 HMMA GEMM + per-class argmin (3-stage) ----------------
// dynamic smem: p2 (1KB); A: 3 x 16KB; B: 3 x 32KB
#define SM_P2    0
#define SM_A     1024
#define TILE_A   16384
#define TILE_BB  32768
#define SM_B     (1024 + 3 * TILE_A)
#define SMEM_TOTAL (1024 + 3 * TILE_A + 3 * TILE_BB)   // 148480

__global__ __launch_bounds__(256, 1) void dist_kernel() {
    extern __shared__ char smem[];
    uint32_t sb = smem_u32(smem);
    const int tid = threadIdx.x;
    const int lane = tid & 31;
    const int wid = tid >> 5;
    const int wm = wid & 1;      // M half (0/1): rows wm*64..+63
    const int wn = wid >> 1;     // N quarter (0..3): cols wn*64..+63 == 2 classes
    const int n0 = blockIdx.x * BN;
    const int m0 = blockIdx.y * BM;

    // p2 tile -> smem
    reinterpret_cast<float*>(smem + SM_P2)[tid] = g_p2[n0 + tid];

    // ---- cp.async loader: i = tid&7 (16B slot), r0 = tid>>3 (row mod 32) ----
    const int li = tid & 7;
    const int r0 = tid >> 3;             // 0..31
    const uint32_t swo = (uint32_t)((li ^ (r0 & 7)) << 4);   // constant per thread
    const __nv_bfloat16* gA = g_Xb + (size_t)(m0 + r0) * NFEAT + li * 8;
    const __nv_bfloat16* gB = g_Wb + (size_t)(n0 + r0) * NFEAT + li * 8;
    uint32_t sA0 = sb + SM_A + r0 * 128 + swo;
    uint32_t sB0 = sb + SM_B + r0 * 128 + swo;

    // prologue: chunks 0,1 -> buffers 0,1
    #pragma unroll
    for (int pc = 0; pc < 2; pc++) {
        #pragma unroll
        for (int it = 0; it < 4; it++)
            cp16(sA0 + pc * TILE_A + it * (32 * 128), gA + pc * KC + (size_t)it * 32 * NFEAT);
        #pragma unroll
        for (int it = 0; it < 8; it++)
            cp16(sB0 + pc * TILE_BB + it * (32 * 128), gB + pc * KC + (size_t)it * 32 * NFEAT);
        asm volatile("cp.async.commit_group;" ::: "memory");
    }

    // ---- ldmatrix lane addressing ----
    const int lr = lane & 7;
    const int lm = lane >> 3;
    const int a_rbase = wm * 64 + (lm & 1) * 8 + lr;
    const int a_chi = lm >> 1;
    const int b_rbase = wn * 64 + (lm >> 1) * 8 + lr;
    const int b_chi = lm & 1;

    float acc[4][8][4];
    #pragma unroll
    for (int i = 0; i < 4; i++)
        #pragma unroll
        for (int j = 0; j < 8; j++)
            #pragma unroll
            for (int k = 0; k < 4; k++) acc[i][j][k] = 0.f;

    #pragma unroll 1
    for (int c = 0; c < NCHUNK; c++) {
        if (c < NCHUNK - 1) asm volatile("cp.async.wait_group 1;" ::: "memory");
        else                asm volatile("cp.async.wait_group 0;" ::: "memory");
        __syncthreads();

        // issue chunk c+2 into buffer (c+2)%3 (whose last reader finished before the sync)
        if (c + 2 < NCHUNK) {
            int nb = (c + 2) % 3;
            const __nv_bfloat16* gA2 = gA + (c + 2) * KC;
            const __nv_bfloat16* gB2 = gB + (c + 2) * KC;
            #pragma unroll
            for (int it = 0; it < 4; it++)
                cp16(sA0 + nb * TILE_A + it * (32 * 128), gA2 + (size_t)it * 32 * NFEAT);
            #pragma unroll
            for (int it = 0; it < 8; it++)
                cp16(sB0 + nb * TILE_BB + it * (32 * 128), gB2 + (size_t)it * 32 * NFEAT);
            asm volatile("cp.async.commit_group;" ::: "memory");
        }

        uint32_t bufA = sb + SM_A + (c % 3) * TILE_A;
        uint32_t bufB = sb + SM_B + (c % 3) * TILE_BB;

        #pragma unroll
        for (int ks = 0; ks < 4; ks++) {
            uint32_t afr[4][4], bfr[4][4];
            #pragma unroll
            for (int i = 0; i < 4; i++) {
                int r = a_rbase + i * 16;
                int ch = ks * 2 + a_chi;
                ldsm4(afr[i], bufA + r * 128 + ((ch ^ (r & 7)) << 4));
            }
            #pragma unroll
            for (int j2 = 0; j2 < 4; j2++) {
                int r = b_rbase + j2 * 16;
                int ch = ks * 2 + b_chi;
                ldsm4(bfr[j2], bufB + r * 128 + ((ch ^ (r & 7)) << 4));
            }
            #pragma unroll
            for (int i = 0; i < 4; i++)
                #pragma unroll
                for (int j = 0; j < 8; j++)
                    mma16816(acc[i][j], afr[i], bfr[j >> 1] + (j & 1) * 2);
        }
    }

    // ---- epilogue: per-(row,class) packed argmin, plain store ----
    const float* sp2 = reinterpret_cast<const float*>(smem + SM_P2);
    const int cls0 = (n0 >> 5) + wn * 2;
    const int colq = 2 * (lane & 3);

    #pragma unroll
    for (int i = 0; i < 4; i++) {
        #pragma unroll
        for (int h = 0; h < 2; h++) {          // class within warp tile
            unsigned long long plo = ~0ull, phi = ~0ull;
            #pragma unroll
            for (int q = 0; q < 4; q++) {
                int j = h * 4 + q;
                #pragma unroll
                for (int t = 0; t < 2; t++) {
                    int colt = wn * 64 + j * 8 + colq + t;
                    float p2v = sp2[colt];
                    unsigned nidx = (unsigned)(n0 + colt);
                    float slo = p2v - 2.0f * acc[i][j][t];
                    plo = umin64(plo, ((unsigned long long)f2ord(slo) << 32) | nidx);
                    float shi = p2v - 2.0f * acc[i][j][2 + t];
                    phi = umin64(phi, ((unsigned long long)f2ord(shi) << 32) | nidx);
                }
            }
            #pragma unroll
            for (int o = 1; o <= 2; o <<= 1) {
                plo = umin64(plo, __shfl_xor_sync(0xffffffffu, plo, o));
                phi = umin64(phi, __shfl_xor_sync(0xffffffffu, phi, o));
            }
            if ((lane & 3) == 0) {
                int row = m0 + wm * 64 + i * 16 + (lane >> 2);
                g_minpack[(size_t)row * NCLS + cls0 + h] = plo;
                g_minpack[(size_t)(row + 8) * NCLS + cls0 + h] = phi;
            }
        }
    }
}

// ---------------- per-row selection: one warp per row ----------------
__global__ __launch_bounds__(256) void select_kernel(const float* __restrict__ X,
                                                     const float* __restrict__ W,
                                                     const int* __restrict__ tgt) {
    const int lane = threadIdx.x & 31;
    const int w = threadIdx.x >> 5;
    const int row = blockIdx.x * 8 + w;
    const int target = tgt[row];

    unsigned long long best = ~0ull, tpk = ~0ull;
    const unsigned long long* mp = g_minpack + (size_t)row * NCLS;
    #pragma unroll
    for (int c = lane; c < NCLS; c += 32) {
        unsigned long long v = mp[c];
        if (c == target) tpk = v;
        else best = umin64(best, v);
    }
    #pragma unroll
    for (int o = 16; o; o >>= 1) {
        best = umin64(best, __shfl_xor_sync(0xffffffffu, best, o));
        tpk  = umin64(tpk,  __shfl_xor_sync(0xffffffffu, tpk,  o));
    }

    int actual_n = (int)(unsigned)(tpk & 0xffffffffull);
    int wrong_n  = (int)(unsigned)(best & 0xffffffffull);

    const float4* xa = reinterpret_cast<const float4*>(X + (size_t)row * NFEAT);
    const float4* pa = reinterpret_cast<const float4*>(W + (size_t)actual_n * NFEAT);
    const float4* pw = reinterpret_cast<const float4*>(W + (size_t)wrong_n  * NFEAT);
    float ts = 0.f, ws = 0.f;
    #pragma unroll
    for (int f = lane; f < NFEAT / 4; f += 32) {
        float4 x = xa[f], a = pa[f], b = pw[f];
        float d;
        d = x.x - a.x; ts += d * d;  d = x.y - a.y; ts += d * d;
        d = x.z - a.z; ts += d * d;  d = x.w - a.w; ts += d * d;
        d = x.x - b.x; ws += d * d;  d = x.y - b.y; ws += d * d;
        d = x.z - b.z; ws += d * d;  d = x.w - b.w; ws += d * d;
    }
    #pragma unroll
    for (int o = 16; o; o >>= 1) {
        ts += __shfl_xor_sync(0xffffffffu, ts, o);
        ws += __shfl_xor_sync(0xffffffffu, ws, o);
    }
    if (lane == 0) {
        g_rowsums[row] = ts;
        g_rowsums[BATCH + row] = ws;
    }
}

__global__ __launch_bounds__(256) void final_kernel(float* __restrict__ out) {
    int t = threadIdx.x;
    float ta = 0.f, wa = 0.f;
    for (int r = t; r < BATCH; r += 256) { ta += g_rowsums[r]; wa += g_rowsums[BATCH + r]; }
    __shared__ float sh[2][8];
    int lane = t & 31, w = t >> 5;
    #pragma unroll
    for (int o = 16; o; o >>= 1) {
        ta += __shfl_down_sync(0xffffffffu, ta, o);
        wa += __shfl_down_sync(0xffffffffu, wa, o);
    }
    if (lane == 0) { sh[0][w] = ta; sh[1][w] = wa; }
    __syncthreads();
    if (t == 0) {
        float ts = 0.f, ws = 0.f;
        #pragma unroll
        for (int i = 0; i < 8; i++) { ts += sh[0][i]; ws += sh[1][i]; }
        float denom = (float)BATCH * (float)NFEAT;
        float tl  = ts / denom;
        float ntl = ws / denom;
        out[0] = (1.0f - ALPHA_F) * tl + ALPHA_F * (1.0f / (ntl + EPS_F));
    }
}

extern "C" void kernel_launch(void* const* d_in, const int* in_sizes, int n_in,
                              void* d_out, int out_size) {
    const float* X   = (const float*)d_in[0];   // outputs [4096, 512]
    const float* W   = (const float*)d_in[1];   // clusters [6400, 512]
    const int*   tgt = (const int*)d_in[2];     // target_classes [4096]
    float* out = (float*)d_out;

    cudaFuncSetAttribute(dist_kernel, cudaFuncAttributeMaxDynamicSharedMemorySize, SMEM_TOTAL);

    conv_kernel<<<CONV_WBLKS + CONV_XBLKS, 256>>>(X, W);
    dim3 grid(NPROT / BN, BATCH / BM);   // (25, 32)
    dist_kernel<<<grid, 256, SMEM_TOTAL>>>();
    select_kernel<<<BATCH / 8, 256>>>(X, W, tgt);
    final_kernel<<<1, 256>>>(out);
}

// round 6
// speedup vs baseline: 5.6618x; 1.0426x over previous
#include <cuda_runtime.h>
#include <cuda_bf16.h>
#include <cstdint>

#define BATCH 4096
#define NCLS  200
#define NFEAT 512
#define NPROT 6400
#define ALPHA_F 5.0f
#define EPS_F   1e-8f

#define BM 128
#define BN 256
#define KC 64                 // bf16 per K-chunk = 128 bytes/row
#define NCHUNK (NFEAT / KC)   // 8

#define SEL_BLOCKS (BATCH / 8)   // 512

// ---------------- device scratch (no runtime allocation) ----------------
__device__ __align__(16) __nv_bfloat16 g_Xb[(size_t)BATCH * NFEAT];
__device__ __align__(16) __nv_bfloat16 g_Wb[(size_t)NPROT * NFEAT];
__device__ float g_p2[NPROT];
__device__ unsigned long long g_minpack[(size_t)BATCH * NCLS];
__device__ float g_acc[2];
__device__ unsigned int g_done;

// ---------------- helpers ----------------
__device__ __forceinline__ uint32_t smem_u32(const void* p) {
    uint32_t a;
    asm("{ .reg .u64 t; cvta.to.shared.u64 t, %1; cvt.u32.u64 %0, t; }" : "=r"(a) : "l"(p));
    return a;
}
__device__ __forceinline__ void cp16(uint32_t s, const void* g) {
    asm volatile("cp.async.cg.shared.global [%0], [%1], 16;" :: "r"(s), "l"(g));
}
__device__ __forceinline__ void ldsm4(uint32_t* r, uint32_t addr) {
    asm volatile("ldmatrix.sync.aligned.m8n8.x4.shared.b16 {%0,%1,%2,%3}, [%4];"
                 : "=r"(r[0]), "=r"(r[1]), "=r"(r[2]), "=r"(r[3]) : "r"(addr));
}
__device__ __forceinline__ void mma16816(float* c, const uint32_t* a, const uint32_t* b) {
    asm volatile("mma.sync.aligned.m16n8k16.row.col.f32.bf16.bf16.f32 "
                 "{%0,%1,%2,%3}, {%4,%5,%6,%7}, {%8,%9}, {%0,%1,%2,%3};"
                 : "+f"(c[0]), "+f"(c[1]), "+f"(c[2]), "+f"(c[3])
                 : "r"(a[0]), "r"(a[1]), "r"(a[2]), "r"(a[3]), "r"(b[0]), "r"(b[1]));
}
__device__ __forceinline__ unsigned int f2ord(float f) {
    unsigned int u = __float_as_uint(f);
    return (u & 0x80000000u) ? ~u : (u | 0x80000000u);
}
__device__ __forceinline__ unsigned long long umin64(unsigned long long a, unsigned long long b) {
    return a < b ? a : b;
}

// ---------------- merged convert kernel ----------------
// blocks 0..3199: two W rows each (bf16 convert + p2)
// blocks 3200..3327: grid-stride bf16 convert of X
#define CONV_WBLKS 3200
#define CONV_XBLKS 128

__global__ __launch_bounds__(256) void conv_kernel(const float* __restrict__ X,
                                                   const float* __restrict__ W) {
    int b = blockIdx.x;
    if (b == 0 && threadIdx.x == 0) {
        g_acc[0] = 0.f; g_acc[1] = 0.f; g_done = 0u;   // reset per replay
    }
    if (b < CONV_WBLKS) {
        int half = threadIdx.x >> 7;          // 0/1: which W row
        int t = threadIdx.x & 127;
        int p = b * 2 + half;
        const float4 v = reinterpret_cast<const float4*>(W + (size_t)p * NFEAT)[t];
        __nv_bfloat162 lo = __nv_bfloat162(__float2bfloat16_rn(v.x), __float2bfloat16_rn(v.y));
        __nv_bfloat162 hi = __nv_bfloat162(__float2bfloat16_rn(v.z), __float2bfloat16_rn(v.w));
        uint2 pk;
        pk.x = *reinterpret_cast<uint32_t*>(&lo);
        pk.y = *reinterpret_cast<uint32_t*>(&hi);
        reinterpret_cast<uint2*>(g_Wb + (size_t)p * NFEAT)[t] = pk;

        float s = v.x * v.x + v.y * v.y + v.z * v.z + v.w * v.w;
        __shared__ float sh[8];
        int lane = threadIdx.x & 31, w = threadIdx.x >> 5;
        #pragma unroll
        for (int o = 16; o; o >>= 1) s += __shfl_down_sync(0xffffffffu, s, o);
        if (lane == 0) sh[w] = s;
        __syncthreads();
        if (t == 0)
            g_p2[p] = sh[half * 4] + sh[half * 4 + 1] + sh[half * 4 + 2] + sh[half * 4 + 3];
    } else {
        int idx = (b - CONV_WBLKS) * 256 + threadIdx.x;
        const int total = BATCH * NFEAT / 4;
        const int stride = CONV_XBLKS * 256;
        for (; idx < total; idx += stride) {
            float4 v = reinterpret_cast<const float4*>(X)[idx];
            __nv_bfloat162 lo = __nv_bfloat162(__float2bfloat16_rn(v.x), __float2bfloat16_rn(v.y));
            __nv_bfloat162 hi = __nv_bfloat162(__float2bfloat16_rn(v.z), __float2bfloat16_rn(v.w));
            uint2 pk;
            pk.x = *reinterpret_cast<uint32_t*>(&lo);
            pk.y = *reinterpret_cast<uint32_t*>(&hi);
            reinterpret_cast<uint2*>(g_Xb)[idx] = pk;
        }
    }
}

// ---------------- fused bf16 HMMA GEMM + per-class argmin (3-stage) ----------------
// dynamic smem: p2 (1KB); A: 3 x 16KB; B: 3 x 32KB
#define SM_P2    0
#define SM_A     1024
#define TILE_A   16384
#define TILE_BB  32768
#define SM_B     (1024 + 3 * TILE_A)
#define SMEM_TOTAL (1024 + 3 * TILE_A + 3 * TILE_BB)   // 148480

__global__ __launch_bounds__(256, 1) void dist_kernel() {
    extern __shared__ char smem[];
    uint32_t sb = smem_u32(smem);
    const int tid = threadIdx.x;
    const int lane = tid & 31;
    const int wid = tid >> 5;
    const int wm = wid & 1;      // M half (0/1): rows wm*64..+63
    const int wn = wid >> 1;     // N quarter (0..3): cols wn*64..+63 == 2 classes
    const int n0 = blockIdx.x * BN;
    const int m0 = blockIdx.y * BM;

    // p2 tile -> smem
    reinterpret_cast<float*>(smem + SM_P2)[tid] = g_p2[n0 + tid];

    // ---- cp.async loader: i = tid&7 (16B slot), r0 = tid>>3 (row mod 32) ----
    const int li = tid & 7;
    const int r0 = tid >> 3;             // 0..31
    const uint32_t swo = (uint32_t)((li ^ (r0 & 7)) << 4);   // constant per thread
    const __nv_bfloat16* gA = g_Xb + (size_t)(m0 + r0) * NFEAT + li * 8;
    const __nv_bfloat16* gB = g_Wb + (size_t)(n0 + r0) * NFEAT + li * 8;
    uint32_t sA0 = sb + SM_A + r0 * 128 + swo;
    uint32_t sB0 = sb + SM_B + r0 * 128 + swo;

    // prologue: chunks 0,1 -> buffers 0,1
    #pragma unroll
    for (int pc = 0; pc < 2; pc++) {
        #pragma unroll
        for (int it = 0; it < 4; it++)
            cp16(sA0 + pc * TILE_A + it * (32 * 128), gA + pc * KC + (size_t)it * 32 * NFEAT);
        #pragma unroll
        for (int it = 0; it < 8; it++)
            cp16(sB0 + pc * TILE_BB + it * (32 * 128), gB + pc * KC + (size_t)it * 32 * NFEAT);
        asm volatile("cp.async.commit_group;" ::: "memory");
    }

    // ---- ldmatrix lane addressing ----
    const int lr = lane & 7;
    const int lm = lane >> 3;
    const int a_rbase = wm * 64 + (lm & 1) * 8 + lr;
    const int a_chi = lm >> 1;
    const int b_rbase = wn * 64 + (lm >> 1) * 8 + lr;
    const int b_chi = lm & 1;

    float acc[4][8][4];
    #pragma unroll
    for (int i = 0; i < 4; i++)
        #pragma unroll
        for (int j = 0; j < 8; j++)
            #pragma unroll
            for (int k = 0; k < 4; k++) acc[i][j][k] = 0.f;

    #pragma unroll 1
    for (int c = 0; c < NCHUNK; c++) {
        if (c < NCHUNK - 1) asm volatile("cp.async.wait_group 1;" ::: "memory");
        else                asm volatile("cp.async.wait_group 0;" ::: "memory");
        __syncthreads();

        // issue chunk c+2 into buffer (c+2)%3 (whose last reader finished before the sync)
        if (c + 2 < NCHUNK) {
            int nb = (c + 2) % 3;
            const __nv_bfloat16* gA2 = gA + (c + 2) * KC;
            const __nv_bfloat16* gB2 = gB + (c + 2) * KC;
            #pragma unroll
            for (int it = 0; it < 4; it++)
                cp16(sA0 + nb * TILE_A + it * (32 * 128), gA2 + (size_t)it * 32 * NFEAT);
            #pragma unroll
            for (int it = 0; it < 8; it++)
                cp16(sB0 + nb * TILE_BB + it * (32 * 128), gB2 + (size_t)it * 32 * NFEAT);
            asm volatile("cp.async.commit_group;" ::: "memory");
        }

        uint32_t bufA = sb + SM_A + (c % 3) * TILE_A;
        uint32_t bufB = sb + SM_B + (c % 3) * TILE_BB;

        #pragma unroll
        for (int ks = 0; ks < 4; ks++) {
            uint32_t afr[4][4], bfr[4][4];
            #pragma unroll
            for (int i = 0; i < 4; i++) {
                int r = a_rbase + i * 16;
                int ch = ks * 2 + a_chi;
                ldsm4(afr[i], bufA + r * 128 + ((ch ^ (r & 7)) << 4));
            }
            #pragma unroll
            for (int j2 = 0; j2 < 4; j2++) {
                int r = b_rbase + j2 * 16;
                int ch = ks * 2 + b_chi;
                ldsm4(bfr[j2], bufB + r * 128 + ((ch ^ (r & 7)) << 4));
            }
            #pragma unroll
            for (int i = 0; i < 4; i++)
                #pragma unroll
                for (int j = 0; j < 8; j++)
                    mma16816(acc[i][j], afr[i], bfr[j >> 1] + (j & 1) * 2);
        }
    }

    // ---- epilogue: per-(row,class) packed argmin, plain store ----
    const float* sp2 = reinterpret_cast<const float*>(smem + SM_P2);
    const int cls0 = (n0 >> 5) + wn * 2;
    const int colq = 2 * (lane & 3);

    // hoist the 16 p2 values this thread touches
    float p2r[8][2];
    #pragma unroll
    for (int j = 0; j < 8; j++) {
        p2r[j][0] = sp2[wn * 64 + j * 8 + colq];
        p2r[j][1] = sp2[wn * 64 + j * 8 + colq + 1];
    }

    #pragma unroll
    for (int i = 0; i < 4; i++) {
        #pragma unroll
        for (int h = 0; h < 2; h++) {          // class within warp tile
            unsigned long long plo = ~0ull, phi = ~0ull;
            #pragma unroll
            for (int q = 0; q < 4; q++) {
                int j = h * 4 + q;
                #pragma unroll
                for (int t = 0; t < 2; t++) {
                    unsigned nidx = (unsigned)(n0 + wn * 64 + j * 8 + colq + t);
                    float p2v = p2r[j][t];
                    float slo = p2v - 2.0f * acc[i][j][t];
                    plo = umin64(plo, ((unsigned long long)f2ord(slo) << 32) | nidx);
                    float shi = p2v - 2.0f * acc[i][j][2 + t];
                    phi = umin64(phi, ((unsigned long long)f2ord(shi) << 32) | nidx);
                }
            }
            #pragma unroll
            for (int o = 1; o <= 2; o <<= 1) {
                plo = umin64(plo, __shfl_xor_sync(0xffffffffu, plo, o));
                phi = umin64(phi, __shfl_xor_sync(0xffffffffu, phi, o));
            }
            if ((lane & 3) == 0) {
                int row = m0 + wm * 64 + i * 16 + (lane >> 2);
                g_minpack[(size_t)row * NCLS + cls0 + h] = plo;
                g_minpack[(size_t)(row + 8) * NCLS + cls0 + h] = phi;
            }
        }
    }
}

// ---------------- selection + fused final reduction (last block finishes) ----------------
__global__ __launch_bounds__(256) void select_kernel(const float* __restrict__ X,
                                                     const float* __restrict__ W,
                                                     const int* __restrict__ tgt,
                                                     float* __restrict__ out) {
    const int lane = threadIdx.x & 31;
    const int w = threadIdx.x >> 5;
    const int row = blockIdx.x * 8 + w;
    const int target = tgt[row];

    unsigned long long best = ~0ull, tpk = ~0ull;
    const unsigned long long* mp = g_minpack + (size_t)row * NCLS;
    #pragma unroll
    for (int c = lane; c < NCLS; c += 32) {
        unsigned long long v = mp[c];
        if (c == target) tpk = v;
        else best = umin64(best, v);
    }
    #pragma unroll
    for (int o = 16; o; o >>= 1) {
        best = umin64(best, __shfl_xor_sync(0xffffffffu, best, o));
        tpk  = umin64(tpk,  __shfl_xor_sync(0xffffffffu, tpk,  o));
    }

    int actual_n = (int)(unsigned)(tpk & 0xffffffffull);
    int wrong_n  = (int)(unsigned)(best & 0xffffffffull);

    const float4* xa = reinterpret_cast<const float4*>(X + (size_t)row * NFEAT);
    const float4* pa = reinterpret_cast<const float4*>(W + (size_t)actual_n * NFEAT);
    const float4* pw = reinterpret_cast<const float4*>(W + (size_t)wrong_n  * NFEAT);
    float ts = 0.f, ws = 0.f;
    #pragma unroll
    for (int f = lane; f < NFEAT / 4; f += 32) {
        float4 x = xa[f], a = pa[f], b = pw[f];
        float d;
        d = x.x - a.x; ts += d * d;  d = x.y - a.y; ts += d * d;
        d = x.z - a.z; ts += d * d;  d = x.w - a.w; ts += d * d;
        d = x.x - b.x; ws += d * d;  d = x.y - b.y; ws += d * d;
        d = x.z - b.z; ws += d * d;  d = x.w - b.w; ws += d * d;
    }
    #pragma unroll
    for (int o = 16; o; o >>= 1) {
        ts += __shfl_xor_sync(0xffffffffu, ts, o);
        ws += __shfl_xor_sync(0xffffffffu, ws, o);
    }

    // block reduce (8 warps), then global atomic accumulate
    __shared__ float shf[2][8];
    if (lane == 0) { shf[0][w] = ts; shf[1][w] = ws; }
    __syncthreads();
    if (threadIdx.x == 0) {
        float a = 0.f, b = 0.f;
        #pragma unroll
        for (int i = 0; i < 8; i++) { a += shf[0][i]; b += shf[1][i]; }
        atomicAdd(&g_acc[0], a);
        atomicAdd(&g_acc[1], b);
        __threadfence();
        unsigned int ticket = atomicAdd(&g_done, 1u);
        if (ticket == SEL_BLOCKS - 1) {
            float tsum = *((volatile float*)&g_acc[0]);
            float wsum = *((volatile float*)&g_acc[1]);
            float denom = (float)BATCH * (float)NFEAT;
            float tl  = tsum / denom;
            float ntl = wsum / denom;
            out[0] = (1.0f - ALPHA_F) * tl + ALPHA_F * (1.0f / (ntl + EPS_F));
        }
    }
}

extern "C" void kernel_launch(void* const* d_in, const int* in_sizes, int n_in,
                              void* d_out, int out_size) {
    const float* X   = (const float*)d_in[0];   // outputs [4096, 512]
    const float* W   = (const float*)d_in[1];   // clusters [6400, 512]
    const int*   tgt = (const int*)d_in[2];     // target_classes [4096]
    float* out = (float*)d_out;

    cudaFuncSetAttribute(dist_kernel, cudaFuncAttributeMaxDynamicSharedMemorySize, SMEM_TOTAL);

    conv_kernel<<<CONV_WBLKS + CONV_XBLKS, 256>>>(X, W);
    dim3 grid(NPROT / BN, BATCH / BM);   // (25, 32)
    dist_kernel<<<grid, 256, SMEM_TOTAL>>>();
    select_kernel<<<SEL_BLOCKS, 256>>>(X, W, tgt, out);
}